// round 9
// baseline (speedup 1.0000x reference)
#include <cuda_runtime.h>
#include <math.h>

#define Bc 4
#define Sc 2
#define Pc 17
#define Wc 128
#define Mc 8
#define Kc 10
#define Cc 34          // (1+TAG)*P
#define HWc 16384
#define BSc 8
#define DET_N (Bc*Sc*Pc*HWc)
#define NCH 34
#define CHUNK 8192
#define NITEM (BSc*Kc*Pc)   // 1360
#define NBLK (2*Pc*BSc)     // 272 blocks (kernel B)
#define KH 5                // k's per block (z-split)

// ---------------- scratch (device globals) ----------------
__device__ double g_det_part[BSc*NCH];
__device__ float  g_cand_v[BSc*NCH*Kc];
__device__ int    g_cand_i[BSc*NCH*Kc];
__device__ double g_hubpart[BSc*Pc*2];
__device__ double g_pushd[BSc];
__device__ double g_pulld[BSc];
__device__ int    g_cnt2 = 0;

#define EINV 0.36787944117144233f

// single-MUFU exp2 (independent of -use_fast_math)
__device__ __forceinline__ float ex2(float x) {
    float r;
    asm("ex2.approx.ftz.f32 %0, %1;" : "=f"(r) : "f"(x));
    return r;
}

// monotone float -> orderable uint
__device__ __forceinline__ unsigned ford(float f) {
    unsigned b = __float_as_uint(f);
    return b ^ ((b & 0x80000000u) ? 0xFFFFFFFFu : 0x80000000u);
}

// branchless register-resident top-10 insertion
__device__ __forceinline__ void insert10(float val, int idx, float* v, int* ix) {
    if (val <= v[Kc - 1]) return;
#pragma unroll
    for (int k = Kc - 1; k > 0; k--) {
        bool shift = val > v[k - 1];
        bool place = val > v[k];
        float nv = shift ? v[k - 1] : (place ? val : v[k]);
        int   ni = shift ? ix[k - 1] : (place ? idx : ix[k]);
        v[k] = nv; ix[k] = ni;
    }
    if (val > v[0]) { v[0] = val; ix[0] = idx; }
}

// ============================================================
// Kernel A: det-BCE partials + per-chunk top-10 candidates
// grid (NCH, BSc) = 272 blocks x 512 threads
// ============================================================
__global__ void __launch_bounds__(512, 2)
scan_kernel(const float* __restrict__ preds,
            const float* __restrict__ gt_masks,
            const float* __restrict__ gt_heatmaps) {
    int ch = blockIdx.x;            // 0..33 : p = ch>>1, half = ch&1
    int bs = blockIdx.y;
    int tid = threadIdx.x;
    int w = tid >> 5;
    int lane = tid & 31;
    int p    = ch >> 1;
    int hw0  = (ch & 1) * CHUNK;
    int b    = bs >> 1;

    const float4* __restrict__ hm4 = (const float4*)(preds + ((size_t)bs * Cc + p) * HWc + hw0);
    const float4* __restrict__ gh4 = (const float4*)(gt_heatmaps + ((size_t)(b * Pc + p)) * HWc + hw0);
    const float4* __restrict__ mk4 = (const float4*)(gt_masks + (size_t)b * HWc + hw0);
    int i0 = ch * CHUNK;

    float v[Kc]; int ix[Kc];
#pragma unroll
    for (int k = 0; k < Kc; k++) { v[k] = -3.0e38f; ix[k] = -1; }
    float facc = 0.0f;

#pragma unroll
    for (int j = 0; j < 4; j++) {
        int idx4 = tid + 512 * j;
        float4 f = hm4[idx4];
        float4 g = gh4[idx4];
        float4 m = mk4[idx4];
        int e = i0 + 4 * idx4;
        insert10(f.x, e + 0, v, ix);
        insert10(f.y, e + 1, v, ix);
        insert10(f.z, e + 2, v, ix);
        insert10(f.w, e + 3, v, ix);
        float hs[4] = {f.x, f.y, f.z, f.w};
        float gs[4] = {g.x, g.y, g.z, g.w};
        float ms[4] = {m.x, m.y, m.z, m.w};
#pragma unroll
        for (int c = 0; c < 4; c++) {
            float prob = __fdividef(1.0f, 1.0f + __expf(-hs[c]));
            float x = prob * ms[c];
            bool selp = gs[c] > EINV;
            float wv  = selp ? 10.0f : ((gs[c] < EINV) ? 0.5f : 0.0f);
            float arg = selp ? x : (1.0f - x);
            facc -= wv * fmaxf(__logf(arg), -100.0f);
        }
    }

    // det: warp reduce float, then serial double over 16 warps
    __shared__ float sdet[16];
#pragma unroll
    for (int o = 16; o > 0; o >>= 1) facc += __shfl_xor_sync(0xffffffffu, facc, o);
    if (lane == 0) sdet[w] = facc;

    // per-warp top-10 via redux argmax (no barriers)
    __shared__ float swv[160];
    __shared__ int   swi[160];
    for (int sel = 0; sel < Kc; sel++) {
        float bv = v[0]; int bidx = ix[0]; int bslot = 0;
#pragma unroll
        for (int j = 1; j < Kc; j++)
            if (v[j] > bv) { bv = v[j]; bidx = ix[j]; bslot = j; }
        unsigned ub = ford(bv);
        unsigned mx = __reduce_max_sync(0xffffffffu, ub);
        unsigned msk = __ballot_sync(0xffffffffu, ub == mx);
        int leader = __ffs(msk) - 1;
        if (lane == leader) {
            swv[w * Kc + sel] = bv;
            swi[w * Kc + sel] = bidx;
#pragma unroll
            for (int j = 0; j < Kc; j++)
                if (j == bslot) v[j] = -3.1e38f;
        }
    }
    __syncthreads();

    // warp 0: merge 160 candidates -> block top-10 (+ det total)
    if (w == 0) {
        float cv[5]; int ci[5];
#pragma unroll
        for (int t = 0; t < 5; t++) {
            cv[t] = swv[lane * 5 + t];
            ci[t] = swi[lane * 5 + t];
        }
        for (int sel = 0; sel < Kc; sel++) {
            float bv = cv[0]; int bidx = ci[0]; int bslot = 0;
#pragma unroll
            for (int t = 1; t < 5; t++)
                if (cv[t] > bv) { bv = cv[t]; bidx = ci[t]; bslot = t; }
            unsigned ub = ford(bv);
            unsigned mx = __reduce_max_sync(0xffffffffu, ub);
            unsigned msk = __ballot_sync(0xffffffffu, ub == mx);
            int leader = __ffs(msk) - 1;
            if (lane == leader) {
                int slot = (bs * NCH + ch) * Kc + sel;
                g_cand_v[slot] = bv;
                g_cand_i[slot] = bidx;
#pragma unroll
                for (int t = 0; t < 5; t++)
                    if (t == bslot) cv[t] = -3.1e38f;
            }
        }
        if (lane == 0) {
            double d = 0.0;
#pragma unroll
            for (int j = 0; j < 16; j++) d += (double)sdet[j];
            g_det_part[bs * NCH + ch] = d;
        }
    }
}

// ============================================================
// Kernel B: per-block redundant top-10 merge + tv/pid, then
// 5-k softmax over (bs,p) plane + fused Huber; push/pull on
// warp 1 of the 8 (z==0,p==0) blocks; last block combines.
// grid (2, Pc, BSc) = 272 blocks x 512 threads, 2 blocks/SM.
// ============================================================
__global__ void __launch_bounds__(512, 2)
softhub_kernel(const float* __restrict__ preds,
               const float* __restrict__ gt_sk,
               const int* __restrict__ gt_kp,
               float* __restrict__ out) {
    int z  = blockIdx.x;
    int p  = blockIdx.y;
    int bs = blockIdx.z;
    int tid = threadIdx.x;
    int w = tid >> 5;
    int lane = tid & 31;
    int b  = bs >> 1;

    __shared__ int    sidx[Kc];
    __shared__ float  stv[Kc];
    __shared__ int    spid[Kc];
    __shared__ float  swarp[16][3 * KH];
    __shared__ float  tot[3 * KH];
    __shared__ double shub[KH];
    __shared__ int    isLast;
    __shared__ double dred[512];

    const float4* __restrict__ hm4 = (const float4*)(preds + ((size_t)bs * Cc + p) * HWc);
    const float4* __restrict__ tg4 = hm4 + (Pc * HWc / 4);

    // ---- warp 0: merge this bs's 340 candidates -> top-10, gather tv, pid ----
    if (w == 0) {
        float cv[11]; int ci[11];
#pragma unroll
        for (int j = 0; j < 11; j++) {
            int c = lane * 11 + j;
            if (c < NCH * Kc) {
                cv[j] = g_cand_v[bs * NCH * Kc + c];
                ci[j] = g_cand_i[bs * NCH * Kc + c];
            } else { cv[j] = -3.3e38f; ci[j] = -1; }
        }
        for (int sel = 0; sel < Kc; sel++) {
            float bv = cv[0]; int bidx = ci[0]; int bslot = 0;
#pragma unroll
            for (int j = 1; j < 11; j++)
                if (cv[j] > bv) { bv = cv[j]; bidx = ci[j]; bslot = j; }
            unsigned ub = ford(bv);
            unsigned mx = __reduce_max_sync(0xffffffffu, ub);
            unsigned msk = __ballot_sync(0xffffffffu, ub == mx);
            int leader = __ffs(msk) - 1;
            if (lane == leader) {
                sidx[sel] = bidx;
#pragma unroll
                for (int j = 0; j < 11; j++)
                    if (j == bslot) cv[j] = -3.3e38f;
            }
        }
        __syncwarp();
        if (lane < Kc) {
            int i  = sidx[lane];
            int tp = i / HWc;
            int hw = i % HWc;
            int xi = hw / Wc;
            int yi = hw % Wc;
            stv[lane] = preds[((size_t)bs * Cc + Pc) * HWc + i];
            float best = 3.4e38f; int bestm = 0;
#pragma unroll
            for (int m = 0; m < Mc; m++) {
                const float* sk = gt_sk + ((b * Mc + m) * Pc + tp) * 3;
                float vp = (sk[2] == 1.0f) ? 256.0f : 0.0f;
                float d0 = vp + sk[1] - (float)xi;
                float d1 = vp + sk[2] - (float)yi;
                float d  = sqrtf(d0 * d0 + d1 * d1 + 1e-12f);
                if (d < best) { best = d; bestm = m; }
            }
            spid[lane] = bestm;
        }
    } else if (w == 1 && z == 0 && p == 0) {
        // ---- push/pull for this bs (lane = m*4 + q) ----
        int m  = lane >> 2;
        int q  = lane & 3;
        int np = (q == 0) ? 5 : 4;
        const float* tb = preds + ((size_t)bs * Cc + Pc) * HWc;
        const int* kpb = gt_kp + ((b * Mc + m) * Pc) * 2;

        float gv[5], vv[5];
        float cnt = 0.0f, sum = 0.0f;
#pragma unroll
        for (int i = 0; i < 5; i++) {
            gv[i] = 0.0f; vv[i] = 0.0f;
            if (i < np) {
                int pp2 = q + 4 * i;
                int idx  = kpb[2 * pp2];
                float vis = (kpb[2 * pp2 + 1] > 0) ? 1.0f : 0.0f;
                float g = tb[idx];
                gv[i] = g; vv[i] = vis;
                cnt += vis; sum += vis * g;
            }
        }
        cnt += __shfl_xor_sync(0xffffffffu, cnt, 1);
        cnt += __shfl_xor_sync(0xffffffffu, cnt, 2);
        sum += __shfl_xor_sync(0xffffffffu, sum, 1);
        sum += __shfl_xor_sync(0xffffffffu, sum, 2);
        float valid = (cnt > 0.0f) ? 1.0f : 0.0f;
        float safe  = fmaxf(cnt, 1.0f);
        float mean  = sum / safe;
        float pp = 0.0f;
#pragma unroll
        for (int i = 0; i < 5; i++) {
            float d = gv[i] - mean;
            pp += d * d * vv[i];
        }
        pp += __shfl_xor_sync(0xffffffffu, pp, 1);
        pp += __shfl_xor_sync(0xffffffffu, pp, 2);
        float pull_m = (pp / safe) * valid;
        float num = valid, pullsum = pull_m;
#pragma unroll
        for (int o = 4; o <= 16; o <<= 1) {
            num     += __shfl_xor_sync(0xffffffffu, num, o);
            pullsum += __shfl_xor_sync(0xffffffffu, pullsum, o);
        }
        float rowsum = 0.0f;
#pragma unroll
        for (int jj = 0; jj < 2; jj++) {
            int j = q + 4 * jj;
            float mj = __shfl_sync(0xffffffffu, mean, j * 4);
            float vj = __shfl_sync(0xffffffffu, valid, j * 4);
            float d = mean - mj;
            rowsum += __expf(-d * d) * valid * vj;
        }
        rowsum += __shfl_xor_sync(0xffffffffu, rowsum, 1);
        rowsum += __shfl_xor_sync(0xffffffffu, rowsum, 2);
        float pmsum = rowsum;
#pragma unroll
        for (int o = 4; o <= 16; o <<= 1)
            pmsum += __shfl_xor_sync(0xffffffffu, pmsum, o);
        if (lane == 0) {
            g_pushd[bs] = (double)((pmsum - num) / ((num - 1.0f) * num + 1e-6f) * 0.5f);
            g_pulld[bs] = (double)(pullsum / (num + 1e-6f));
        }
    } else {
        // ---- other warps: L2-prefetch this block's tag plane (cold DRAM)
        // while warp 0 merges; overlaps the serial prologue.
#pragma unroll
        for (int j = 0; j < 8; j++) {
            const float4* a = tg4 + (tid + 512 * j);
            asm volatile("prefetch.global.L2 [%0];" :: "l"(a));
        }
    }
    __syncthreads();

    // ---- softmax sums for k in [5z, 5z+5) over full plane ----
    {
        const float C1 = 4.328085122666891f;     // 3 * log2(e)
        const float C2 = 18.033688011112047f;    // 12.5 * log2(e)
        const float TWOC2 = 36.067376022224094f;
        float hmax = fmaxf(g_cand_v[(bs * NCH + 2 * p) * Kc],
                           g_cand_v[(bs * NCH + 2 * p + 1) * Kc]);
        float L = C1 * hmax;

        float tv[KH], tvq[KH];
#pragma unroll
        for (int k = 0; k < KH; k++) {
            float t = stv[z * KH + k];
            tv[k] = t;
            tvq[k] = -C2 * t * t;
        }

        float se[KH], sx[KH], sy[KH];
#pragma unroll
        for (int k = 0; k < KH; k++) { se[k] = 0.0f; sx[k] = 0.0f; sy[k] = 0.0f; }

#pragma unroll 2
        for (int j = 0; j < 8; j++) {
            int idx4 = tid + 512 * j;
            float4 h = hm4[idx4];
            float4 t = tg4[idx4];
            int e0 = 4 * idx4;
            float xf = (float)(e0 >> 7);          // row constant within float4
            float yb = (float)(e0 & 127);
            float b0 = fmaf(C1, h.x, -L), b1 = fmaf(C1, h.y, -L);
            float b2 = fmaf(C1, h.z, -L), b3 = fmaf(C1, h.w, -L);
            float A0 = fmaf(t.x * (-C2), t.x, b0), B0 = t.x * TWOC2;
            float A1 = fmaf(t.y * (-C2), t.y, b1), B1 = t.y * TWOC2;
            float A2_ = fmaf(t.z * (-C2), t.z, b2), B2 = t.z * TWOC2;
            float A3 = fmaf(t.w * (-C2), t.w, b3), B3 = t.w * TWOC2;
#pragma unroll
            for (int k = 0; k < KH; k++) {
                float e0f = ex2(fmaf(B0, tv[k], A0) + tvq[k]);
                float e1f = ex2(fmaf(B1, tv[k], A1) + tvq[k]);
                float e2f = ex2(fmaf(B2, tv[k], A2_) + tvq[k]);
                float e3f = ex2(fmaf(B3, tv[k], A3) + tvq[k]);
                float srow = (e0f + e1f) + (e2f + e3f);
                se[k] += srow;
                sx[k] = fmaf(srow, xf, sx[k]);
                // sum e_c*(yb+c) = yb*srow + e1 + 2e2 + 3e3
                float u = fmaf(e2f, 2.0f, e1f);
                u = fmaf(e3f, 3.0f, u);
                sy[k] = fmaf(srow, yb, sy[k]);
                sy[k] += u;
            }
        }

#pragma unroll
        for (int o = 16; o > 0; o >>= 1) {
#pragma unroll
            for (int k = 0; k < KH; k++) {
                se[k] += __shfl_xor_sync(0xffffffffu, se[k], o);
                sx[k] += __shfl_xor_sync(0xffffffffu, sx[k], o);
                sy[k] += __shfl_xor_sync(0xffffffffu, sy[k], o);
            }
        }
        if (lane == 0) {
#pragma unroll
            for (int k = 0; k < KH; k++) {
                swarp[w][k]          = se[k];
                swarp[w][KH + k]     = sx[k];
                swarp[w][2 * KH + k] = sy[k];
            }
        }
        __syncthreads();
        if (tid < 3 * KH) {
            float s = 0.0f;
#pragma unroll
            for (int ww = 0; ww < 16; ww++) s += swarp[ww][tid];
            tot[tid] = s;
        }
        __syncthreads();

        // Huber for this block's 5 ks
        if (tid < KH) {
            int kg = z * KH + tid;
            float seT = tot[tid], sxT = tot[KH + tid], syT = tot[2 * KH + tid];
            float inv = 1.0f / seT;
            float px = sxT * inv, py = syT * inv;
            int pid = spid[kg];
            const float* sk = gt_sk + ((b * Mc + pid) * Pc + p) * 3;
            float ex = sk[0] - px;
            float ey = sk[1] - py;
            float err = sqrtf(ex * ex + ey * ey + 1e-12f) * ((sk[2] > 0.0f) ? 1.0f : 0.0f);
            float a = fabsf(err);
            shub[tid] = (double)((a < 0.1f) ? (err * err) : (0.1f * (a - 0.05f)));
        }
        __syncthreads();
        if (tid == 0) {
            double s = 0.0;
#pragma unroll
            for (int k = 0; k < KH; k++) s += shub[k];
            g_hubpart[(bs * Pc + p) * 2 + z] = s;
        }
    }

    // ---- last block: final combine ----
    __threadfence();
    if (tid == 0) isLast = (atomicAdd(&g_cnt2, 1) == NBLK - 1) ? 1 : 0;
    __syncthreads();
    if (!isLast) return;
    __threadfence();

    double hacc = 0.0, dacc = 0.0;
    for (int j = tid; j < BSc * Pc * 2; j += 512) hacc += g_hubpart[j];
    for (int j = tid; j < BSc * NCH; j += 512) dacc += g_det_part[j];
    dred[tid] = hacc;
    __shared__ double dred2[512];
    dred2[tid] = dacc;
    __syncthreads();
    for (int o = 256; o > 0; o >>= 1) {
        if (tid < o) { dred[tid] += dred[tid + o]; dred2[tid] += dred2[tid + o]; }
        __syncthreads();
    }
    if (tid == 0) {
        double sp = 0.0, sl = 0.0;
        for (int j = 0; j < BSc; j++) { sp += g_pushd[j]; sl += g_pulld[j]; }
        double det = dred2[0] / (double)DET_N;
        double total = sp / 8.0 + sl / 8.0 + det + 10.0 * dred[0] / (double)NITEM;
        out[0] = (float)total;
        g_cnt2 = 0;           // reset for graph replay
    }
}

// ============================================================
extern "C" void kernel_launch(void* const* d_in, const int* in_sizes, int n_in,
                              void* d_out, int out_size) {
    const float* preds       = (const float*)d_in[0];
    const float* gt_masks    = (const float*)d_in[1];
    const float* gt_heatmaps = (const float*)d_in[2];
    const float* gt_sk       = (const float*)d_in[3];
    const int*   gt_kp       = (const int*)d_in[4];

    scan_kernel<<<dim3(NCH, BSc), 512>>>(preds, gt_masks, gt_heatmaps);
    softhub_kernel<<<dim3(2, Pc, BSc), 512>>>(preds, gt_sk, gt_kp, (float*)d_out);
}

// round 10
// speedup vs baseline: 1.2509x; 1.2509x over previous
#include <cuda_runtime.h>
#include <math.h>

#define Bc 4
#define Sc 2
#define Pc 17
#define Wc 128
#define Mc 8
#define Kc 10
#define Cc 34          // (1+TAG)*P
#define HWc 16384
#define BSc 8
#define DET_N (Bc*Sc*Pc*HWc)
#define NCH 34
#define CHUNK 8192
#define NITEM (BSc*Kc*Pc)   // 1360
#define NBLK (Pc*BSc)       // 136 blocks (kernel B)

// ---------------- scratch (device globals) ----------------
__device__ double g_det_part[BSc*NCH];
__device__ float  g_cand_v[BSc*NCH*Kc];
__device__ int    g_cand_i[BSc*NCH*Kc];
__device__ double g_hubpart[BSc*Pc];
__device__ double g_pushd[BSc];
__device__ double g_pulld[BSc];
__device__ int    g_cnt2 = 0;

#define EINV 0.36787944117144233f

// single-MUFU exp2
__device__ __forceinline__ float ex2(float x) {
    float r;
    asm("ex2.approx.ftz.f32 %0, %1;" : "=f"(r) : "f"(x));
    return r;
}

// monotone float -> orderable uint
__device__ __forceinline__ unsigned ford(float f) {
    unsigned b = __float_as_uint(f);
    return b ^ ((b & 0x80000000u) ? 0xFFFFFFFFu : 0x80000000u);
}

// branchless register-resident top-10 insertion
__device__ __forceinline__ void insert10(float val, int idx, float* v, int* ix) {
    if (val <= v[Kc - 1]) return;
#pragma unroll
    for (int k = Kc - 1; k > 0; k--) {
        bool shift = val > v[k - 1];
        bool place = val > v[k];
        float nv = shift ? v[k - 1] : (place ? val : v[k]);
        int   ni = shift ? ix[k - 1] : (place ? idx : ix[k]);
        v[k] = nv; ix[k] = ni;
    }
    if (val > v[0]) { v[0] = val; ix[0] = idx; }
}

// ============================================================
// Kernel A: det-BCE partials + per-chunk top-10 candidates
// grid (NCH, BSc) = 272 blocks x 512 threads  (round-8 proven)
// ============================================================
__global__ void __launch_bounds__(512, 2)
scan_kernel(const float* __restrict__ preds,
            const float* __restrict__ gt_masks,
            const float* __restrict__ gt_heatmaps) {
    int ch = blockIdx.x;            // 0..33 : p = ch>>1, half = ch&1
    int bs = blockIdx.y;
    int tid = threadIdx.x;
    int w = tid >> 5;
    int lane = tid & 31;
    int p    = ch >> 1;
    int hw0  = (ch & 1) * CHUNK;
    int b    = bs >> 1;

    const float4* __restrict__ hm4 = (const float4*)(preds + ((size_t)bs * Cc + p) * HWc + hw0);
    const float4* __restrict__ gh4 = (const float4*)(gt_heatmaps + ((size_t)(b * Pc + p)) * HWc + hw0);
    const float4* __restrict__ mk4 = (const float4*)(gt_masks + (size_t)b * HWc + hw0);
    int i0 = ch * CHUNK;

    float v[Kc]; int ix[Kc];
#pragma unroll
    for (int k = 0; k < Kc; k++) { v[k] = -3.0e38f; ix[k] = -1; }
    float facc = 0.0f;

#pragma unroll
    for (int j = 0; j < 4; j++) {
        int idx4 = tid + 512 * j;
        float4 f = hm4[idx4];
        float4 g = gh4[idx4];
        float4 m = mk4[idx4];
        int e = i0 + 4 * idx4;
        insert10(f.x, e + 0, v, ix);
        insert10(f.y, e + 1, v, ix);
        insert10(f.z, e + 2, v, ix);
        insert10(f.w, e + 3, v, ix);
        float hs[4] = {f.x, f.y, f.z, f.w};
        float gs[4] = {g.x, g.y, g.z, g.w};
        float ms[4] = {m.x, m.y, m.z, m.w};
#pragma unroll
        for (int c = 0; c < 4; c++) {
            float prob = __fdividef(1.0f, 1.0f + __expf(-hs[c]));
            float x = prob * ms[c];
            bool selp = gs[c] > EINV;
            float wv  = selp ? 10.0f : ((gs[c] < EINV) ? 0.5f : 0.0f);
            float arg = selp ? x : (1.0f - x);
            facc -= wv * fmaxf(__logf(arg), -100.0f);
        }
    }

    // det: warp reduce float, then serial double over 16 warps
    __shared__ float sdet[16];
#pragma unroll
    for (int o = 16; o > 0; o >>= 1) facc += __shfl_xor_sync(0xffffffffu, facc, o);
    if (lane == 0) sdet[w] = facc;

    // per-warp top-10 via redux argmax (no barriers)
    __shared__ float swv[160];
    __shared__ int   swi[160];
    for (int sel = 0; sel < Kc; sel++) {
        float bv = v[0]; int bidx = ix[0]; int bslot = 0;
#pragma unroll
        for (int j = 1; j < Kc; j++)
            if (v[j] > bv) { bv = v[j]; bidx = ix[j]; bslot = j; }
        unsigned ub = ford(bv);
        unsigned mx = __reduce_max_sync(0xffffffffu, ub);
        unsigned msk = __ballot_sync(0xffffffffu, ub == mx);
        int leader = __ffs(msk) - 1;
        if (lane == leader) {
            swv[w * Kc + sel] = bv;
            swi[w * Kc + sel] = bidx;
#pragma unroll
            for (int j = 0; j < Kc; j++)
                if (j == bslot) v[j] = -3.1e38f;
        }
    }
    __syncthreads();

    // warp 0: merge 160 candidates -> block top-10 (+ det total)
    if (w == 0) {
        float cv[5]; int ci[5];
#pragma unroll
        for (int t = 0; t < 5; t++) {
            cv[t] = swv[lane * 5 + t];
            ci[t] = swi[lane * 5 + t];
        }
        for (int sel = 0; sel < Kc; sel++) {
            float bv = cv[0]; int bidx = ci[0]; int bslot = 0;
#pragma unroll
            for (int t = 1; t < 5; t++)
                if (cv[t] > bv) { bv = cv[t]; bidx = ci[t]; bslot = t; }
            unsigned ub = ford(bv);
            unsigned mx = __reduce_max_sync(0xffffffffu, ub);
            unsigned msk = __ballot_sync(0xffffffffu, ub == mx);
            int leader = __ffs(msk) - 1;
            if (lane == leader) {
                int slot = (bs * NCH + ch) * Kc + sel;
                g_cand_v[slot] = bv;
                g_cand_i[slot] = bidx;
#pragma unroll
                for (int t = 0; t < 5; t++)
                    if (t == bslot) cv[t] = -3.1e38f;
            }
        }
        if (lane == 0) {
            double d = 0.0;
#pragma unroll
            for (int j = 0; j < 16; j++) d += (double)sdet[j];
            g_det_part[bs * NCH + ch] = d;
        }
    }
}

// ============================================================
// Kernel B: per-block redundant top-10 merge + tv/pid, then
// ALL-10-k softmax over (bs,p) plane (read once) + fused Huber;
// push/pull on warp 1 of p==0 blocks; last block combines.
// grid (Pc, BSc) = 136 blocks x 512 threads.
// ============================================================
__global__ void __launch_bounds__(512)
softhub_kernel(const float* __restrict__ preds,
               const float* __restrict__ gt_sk,
               const int* __restrict__ gt_kp,
               float* __restrict__ out) {
    int p  = blockIdx.x;
    int bs = blockIdx.y;
    int tid = threadIdx.x;
    int w = tid >> 5;
    int lane = tid & 31;
    int b  = bs >> 1;

    __shared__ int    sidx[Kc];
    __shared__ float  stv[Kc];
    __shared__ int    spid[Kc];
    __shared__ float  swarp[16][3 * Kc];
    __shared__ float  tot[3 * Kc];
    __shared__ double shub[Kc];
    __shared__ int    isLast;
    __shared__ double dred[512];

    const float4* __restrict__ hm4 = (const float4*)(preds + ((size_t)bs * Cc + p) * HWc);
    const float4* __restrict__ tg4 = hm4 + (Pc * HWc / 4);

    // ---- warp 0: merge this bs's 340 candidates -> top-10, gather tv, pid ----
    if (w == 0) {
        float cv[11]; int ci[11];
#pragma unroll
        for (int j = 0; j < 11; j++) {
            int c = lane * 11 + j;
            if (c < NCH * Kc) {
                cv[j] = g_cand_v[bs * NCH * Kc + c];
                ci[j] = g_cand_i[bs * NCH * Kc + c];
            } else { cv[j] = -3.3e38f; ci[j] = -1; }
        }
        for (int sel = 0; sel < Kc; sel++) {
            float bv = cv[0]; int bidx = ci[0]; int bslot = 0;
#pragma unroll
            for (int j = 1; j < 11; j++)
                if (cv[j] > bv) { bv = cv[j]; bidx = ci[j]; bslot = j; }
            unsigned ub = ford(bv);
            unsigned mx = __reduce_max_sync(0xffffffffu, ub);
            unsigned msk = __ballot_sync(0xffffffffu, ub == mx);
            int leader = __ffs(msk) - 1;
            if (lane == leader) {
                sidx[sel] = bidx;
#pragma unroll
                for (int j = 0; j < 11; j++)
                    if (j == bslot) cv[j] = -3.3e38f;
            }
        }
        __syncwarp();
        if (lane < Kc) {
            int i  = sidx[lane];
            int tp = i / HWc;
            int hw = i % HWc;
            int xi = hw / Wc;
            int yi = hw % Wc;
            stv[lane] = preds[((size_t)bs * Cc + Pc) * HWc + i];
            float best = 3.4e38f; int bestm = 0;
#pragma unroll
            for (int m = 0; m < Mc; m++) {
                const float* sk = gt_sk + ((b * Mc + m) * Pc + tp) * 3;
                float vp = (sk[2] == 1.0f) ? 256.0f : 0.0f;
                float d0 = vp + sk[1] - (float)xi;
                float d1 = vp + sk[2] - (float)yi;
                float d  = sqrtf(d0 * d0 + d1 * d1 + 1e-12f);
                if (d < best) { best = d; bestm = m; }
            }
            spid[lane] = bestm;
        }
    } else if (w == 1 && p == 0) {
        // ---- push/pull for this bs (lane = m*4 + q) ----
        int m  = lane >> 2;
        int q  = lane & 3;
        int np = (q == 0) ? 5 : 4;
        const float* tb = preds + ((size_t)bs * Cc + Pc) * HWc;
        const int* kpb = gt_kp + ((b * Mc + m) * Pc) * 2;

        float gv[5], vv[5];
        float cnt = 0.0f, sum = 0.0f;
#pragma unroll
        for (int i = 0; i < 5; i++) {
            gv[i] = 0.0f; vv[i] = 0.0f;
            if (i < np) {
                int pp2 = q + 4 * i;
                int idx  = kpb[2 * pp2];
                float vis = (kpb[2 * pp2 + 1] > 0) ? 1.0f : 0.0f;
                float g = tb[idx];
                gv[i] = g; vv[i] = vis;
                cnt += vis; sum += vis * g;
            }
        }
        cnt += __shfl_xor_sync(0xffffffffu, cnt, 1);
        cnt += __shfl_xor_sync(0xffffffffu, cnt, 2);
        sum += __shfl_xor_sync(0xffffffffu, sum, 1);
        sum += __shfl_xor_sync(0xffffffffu, sum, 2);
        float valid = (cnt > 0.0f) ? 1.0f : 0.0f;
        float safe  = fmaxf(cnt, 1.0f);
        float mean  = sum / safe;
        float pp = 0.0f;
#pragma unroll
        for (int i = 0; i < 5; i++) {
            float d = gv[i] - mean;
            pp += d * d * vv[i];
        }
        pp += __shfl_xor_sync(0xffffffffu, pp, 1);
        pp += __shfl_xor_sync(0xffffffffu, pp, 2);
        float pull_m = (pp / safe) * valid;
        float num = valid, pullsum = pull_m;
#pragma unroll
        for (int o = 4; o <= 16; o <<= 1) {
            num     += __shfl_xor_sync(0xffffffffu, num, o);
            pullsum += __shfl_xor_sync(0xffffffffu, pullsum, o);
        }
        float rowsum = 0.0f;
#pragma unroll
        for (int jj = 0; jj < 2; jj++) {
            int j = q + 4 * jj;
            float mj = __shfl_sync(0xffffffffu, mean, j * 4);
            float vj = __shfl_sync(0xffffffffu, valid, j * 4);
            float d = mean - mj;
            rowsum += __expf(-d * d) * valid * vj;
        }
        rowsum += __shfl_xor_sync(0xffffffffu, rowsum, 1);
        rowsum += __shfl_xor_sync(0xffffffffu, rowsum, 2);
        float pmsum = rowsum;
#pragma unroll
        for (int o = 4; o <= 16; o <<= 1)
            pmsum += __shfl_xor_sync(0xffffffffu, pmsum, o);
        if (lane == 0) {
            g_pushd[bs] = (double)((pmsum - num) / ((num - 1.0f) * num + 1e-6f) * 0.5f);
            g_pulld[bs] = (double)(pullsum / (num + 1e-6f));
        }
    }
    __syncthreads();

    // ---- softmax sums for ALL 10 k over full plane (each element once) ----
    {
        const float C1 = 4.328085122666891f;     // 3 * log2(e)
        const float C2 = 18.033688011112047f;    // 12.5 * log2(e)
        const float TWOC2 = 36.067376022224094f;
        float hmax = fmaxf(g_cand_v[(bs * NCH + 2 * p) * Kc],
                           g_cand_v[(bs * NCH + 2 * p + 1) * Kc]);
        float L = C1 * hmax;

        float tv[Kc], tvq[Kc];
#pragma unroll
        for (int k = 0; k < Kc; k++) {
            float t = stv[k];
            tv[k] = t;
            tvq[k] = -C2 * t * t;
        }

        float se[Kc], sx[Kc], sy[Kc];
#pragma unroll
        for (int k = 0; k < Kc; k++) { se[k] = 0.0f; sx[k] = 0.0f; sy[k] = 0.0f; }

#pragma unroll 2
        for (int j = 0; j < 8; j++) {
            int idx4 = tid + 512 * j;
            float4 h = hm4[idx4];
            float4 t = tg4[idx4];
            int e0 = 4 * idx4;
            float xf = (float)(e0 >> 7);          // row constant within float4
            float yb = (float)(e0 & 127);
            float b0 = fmaf(C1, h.x, -L), b1 = fmaf(C1, h.y, -L);
            float b2 = fmaf(C1, h.z, -L), b3 = fmaf(C1, h.w, -L);
            float A0 = fmaf(t.x * (-C2), t.x, b0), B0 = t.x * TWOC2;
            float A1 = fmaf(t.y * (-C2), t.y, b1), B1 = t.y * TWOC2;
            float A2_ = fmaf(t.z * (-C2), t.z, b2), B2 = t.z * TWOC2;
            float A3 = fmaf(t.w * (-C2), t.w, b3), B3 = t.w * TWOC2;
#pragma unroll
            for (int k = 0; k < Kc; k++) {
                float e0f = ex2(fmaf(B0, tv[k], A0) + tvq[k]);
                float e1f = ex2(fmaf(B1, tv[k], A1) + tvq[k]);
                float e2f = ex2(fmaf(B2, tv[k], A2_) + tvq[k]);
                float e3f = ex2(fmaf(B3, tv[k], A3) + tvq[k]);
                float srow = (e0f + e1f) + (e2f + e3f);
                se[k] += srow;
                sx[k] = fmaf(srow, xf, sx[k]);
                // sum e_c*(yb+c) = yb*srow + e1 + 2e2 + 3e3
                float u = fmaf(e2f, 2.0f, e1f);
                u = fmaf(e3f, 3.0f, u);
                sy[k] = fmaf(srow, yb, sy[k]);
                sy[k] += u;
            }
        }

#pragma unroll
        for (int o = 16; o > 0; o >>= 1) {
#pragma unroll
            for (int k = 0; k < Kc; k++) {
                se[k] += __shfl_xor_sync(0xffffffffu, se[k], o);
                sx[k] += __shfl_xor_sync(0xffffffffu, sx[k], o);
                sy[k] += __shfl_xor_sync(0xffffffffu, sy[k], o);
            }
        }
        if (lane == 0) {
#pragma unroll
            for (int k = 0; k < Kc; k++) {
                swarp[w][k]          = se[k];
                swarp[w][Kc + k]     = sx[k];
                swarp[w][2 * Kc + k] = sy[k];
            }
        }
        __syncthreads();
        if (tid < 3 * Kc) {
            float s = 0.0f;
#pragma unroll
            for (int ww = 0; ww < 16; ww++) s += swarp[ww][tid];
            tot[tid] = s;
        }
        __syncthreads();

        // Huber for all 10 ks
        if (tid < Kc) {
            float seT = tot[tid], sxT = tot[Kc + tid], syT = tot[2 * Kc + tid];
            float inv = 1.0f / seT;
            float px = sxT * inv, py = syT * inv;
            int pid = spid[tid];
            const float* sk = gt_sk + ((b * Mc + pid) * Pc + p) * 3;
            float ex = sk[0] - px;
            float ey = sk[1] - py;
            float err = sqrtf(ex * ex + ey * ey + 1e-12f) * ((sk[2] > 0.0f) ? 1.0f : 0.0f);
            float a = fabsf(err);
            shub[tid] = (double)((a < 0.1f) ? (err * err) : (0.1f * (a - 0.05f)));
        }
        __syncthreads();
        if (tid == 0) {
            double s = 0.0;
#pragma unroll
            for (int k = 0; k < Kc; k++) s += shub[k];
            g_hubpart[bs * Pc + p] = s;
        }
    }

    // ---- last block: final combine ----
    __threadfence();
    if (tid == 0) isLast = (atomicAdd(&g_cnt2, 1) == NBLK - 1) ? 1 : 0;
    __syncthreads();
    if (!isLast) return;
    __threadfence();

    double hacc = 0.0, dacc = 0.0;
    for (int j = tid; j < BSc * Pc; j += 512) hacc += g_hubpart[j];
    for (int j = tid; j < BSc * NCH; j += 512) dacc += g_det_part[j];
    dred[tid] = hacc;
    __shared__ double dred2[512];
    dred2[tid] = dacc;
    __syncthreads();
    for (int o = 256; o > 0; o >>= 1) {
        if (tid < o) { dred[tid] += dred[tid + o]; dred2[tid] += dred2[tid + o]; }
        __syncthreads();
    }
    if (tid == 0) {
        double sp = 0.0, sl = 0.0;
        for (int j = 0; j < BSc; j++) { sp += g_pushd[j]; sl += g_pulld[j]; }
        double det = dred2[0] / (double)DET_N;
        double total = sp / 8.0 + sl / 8.0 + det + 10.0 * dred[0] / (double)NITEM;
        out[0] = (float)total;
        g_cnt2 = 0;           // reset for graph replay
    }
}

// ============================================================
extern "C" void kernel_launch(void* const* d_in, const int* in_sizes, int n_in,
                              void* d_out, int out_size) {
    const float* preds       = (const float*)d_in[0];
    const float* gt_masks    = (const float*)d_in[1];
    const float* gt_heatmaps = (const float*)d_in[2];
    const float* gt_sk       = (const float*)d_in[3];
    const int*   gt_kp       = (const int*)d_in[4];

    scan_kernel<<<dim3(NCH, BSc), 512>>>(preds, gt_masks, gt_heatmaps);
    softhub_kernel<<<dim3(Pc, BSc), 512>>>(preds, gt_sk, gt_kp, (float*)d_out);
}